// round 5
// baseline (speedup 1.0000x reference)
#include <cuda_runtime.h>

// IntraLoss: loss = (1/N) * sum_n || features[n] - center[labels[n]] ||_2
// N=32768, C=1000, D=512. features f32 [N,D], labels int32 [N], center f32 [C,D].
//
// Pipeline (4 launches, graph-capturable, no allocations):
//   1. histogram: counts[c] = #samples with label c           (global atomics)
//   2. scan: base[c] = exclusive prefix of counts; cursor=base (1 block)
//   3. scatter: order[base[l]+k] = sample_idx | (l << 20)      (atomic cursors)
//   4. main: process samples in sorted order -> center rows are L1-hot.
//      Last block reduces partials, writes out, resets globals for replay.

#define NROWS 32768
#define NCLS  1000
#define DDIM  512
#define NBLK  1024

__device__ float g_partials[NBLK];
__device__ unsigned int g_counter = 0;
__device__ int g_counts[NCLS];      // zero-initialized; reset by main kernel tail
__device__ int g_base[NCLS];
__device__ int g_cursor[NCLS];
__device__ int g_order[NROWS];

// ---------- 1. histogram ----------
__global__ __launch_bounds__(256) void hist_kernel(const int* __restrict__ labels)
{
    int i = blockIdx.x * 256 + threadIdx.x;      // 128 blocks x 256 = 32768
    int lbl = labels[i];
    lbl = min(max(lbl, 0), NCLS - 1);
    atomicAdd(&g_counts[lbl], 1);
}

// ---------- 2. exclusive scan over 1000 counts (1 block, 1024 threads) ----------
__global__ __launch_bounds__(1024) void scan_kernel()
{
    __shared__ int s[1024];
    int t = threadIdx.x;
    int c = (t < NCLS) ? g_counts[t] : 0;
    s[t] = c;
    __syncthreads();
    #pragma unroll
    for (int off = 1; off < 1024; off <<= 1) {
        int v = (t >= off) ? s[t - off] : 0;
        __syncthreads();
        s[t] += v;
        __syncthreads();
    }
    if (t < NCLS) {
        int base = s[t] - c;     // exclusive
        g_base[t] = base;
        g_cursor[t] = base;
    }
}

// ---------- 3. scatter: build sorted order with packed label ----------
__global__ __launch_bounds__(256) void scatter_kernel(const int* __restrict__ labels)
{
    int i = blockIdx.x * 256 + threadIdx.x;      // 128 blocks x 256 = 32768
    int lbl = labels[i];
    lbl = min(max(lbl, 0), NCLS - 1);
    int k = atomicAdd(&g_cursor[lbl], 1);
    g_order[k] = i | (lbl << 20);                // row in [0,32768), lbl in [0,1000)
}

// ---------- 4. main ----------
__global__ __launch_bounds__(256) void intra_loss_kernel(
    const float4* __restrict__ feats,    // [N, D/4]
    const float4* __restrict__ center,   // [C, D/4]
    float* __restrict__ out)
{
    const int lane  = threadIdx.x & 31;
    const int wib   = threadIdx.x >> 5;                      // 0..7
    const int warpG = (blockIdx.x << 3) + wib;               // 0..8191
    const int g     = lane >> 3;                             // group 0..3
    const int l     = lane & 7;                              // lane in group
    const int pos   = (warpG << 2) + g;                      // sorted position

    const int e   = g_order[pos];
    const int row = e & 0xFFFFF;
    const int lbl = e >> 20;

    const float4* fr = feats  + (size_t)row * (DDIM / 4);
    const float4* cr = center + (size_t)lbl * (DDIM / 4);

    float acc = 0.0f;
    #pragma unroll
    for (int i = 0; i < 16; i++) {
        float4 a = __ldcs(&fr[l + i * 8]);   // stream features (read once)
        float4 b = __ldg(&cr[l + i * 8]);    // center: L1-hot (shared labels)
        float dx = a.x - b.x;
        float dy = a.y - b.y;
        float dz = a.z - b.z;
        float dw = a.w - b.w;
        acc = fmaf(dx, dx, acc);
        acc = fmaf(dy, dy, acc);
        acc = fmaf(dz, dz, acc);
        acc = fmaf(dw, dw, acc);
    }

    // reduce within 8-lane group (all 4 rows in parallel)
    acc += __shfl_xor_sync(0xffffffffu, acc, 1);
    acc += __shfl_xor_sync(0xffffffffu, acc, 2);
    acc += __shfl_xor_sync(0xffffffffu, acc, 4);

    float d = (l == 0) ? sqrtf(acc) : 0.0f;

    d += __shfl_xor_sync(0xffffffffu, d, 8);
    d += __shfl_xor_sync(0xffffffffu, d, 16);

    __shared__ float smem[8];
    __shared__ bool is_last;
    if (lane == 0) smem[wib] = d;
    __syncthreads();

    if (threadIdx.x == 0) {
        float s = 0.0f;
        #pragma unroll
        for (int i = 0; i < 8; i++) s += smem[i];
        g_partials[blockIdx.x] = s;
        __threadfence();
        unsigned int old = atomicAdd(&g_counter, 1u);
        is_last = (old == NBLK - 1);
    }
    __syncthreads();

    if (is_last) {
        float v = 0.0f;
        #pragma unroll
        for (int i = 0; i < 4; i++)
            v += g_partials[threadIdx.x + i * 256];

        #pragma unroll
        for (int s = 16; s > 0; s >>= 1)
            v += __shfl_xor_sync(0xffffffffu, v, s);

        __shared__ float smem2[8];
        if (lane == 0) smem2[wib] = v;
        __syncthreads();

        if (threadIdx.x == 0) {
            float w = 0.0f;
            #pragma unroll
            for (int i = 0; i < 8; i++) w += smem2[i];
            out[0] = w * (1.0f / (float)NROWS);
            g_counter = 0;
        }
        // reset counts for next graph replay (1000 ints, 256 threads)
        for (int i = threadIdx.x; i < NCLS; i += 256) g_counts[i] = 0;
    }
}

extern "C" void kernel_launch(void* const* d_in, const int* in_sizes, int n_in,
                              void* d_out, int out_size)
{
    const float4* feats  = (const float4*)d_in[0];
    const int* labels    = (const int*)d_in[1];
    const float4* center = (const float4*)d_in[2];
    float* out           = (float*)d_out;

    hist_kernel<<<NROWS / 256, 256>>>(labels);
    scan_kernel<<<1, 1024>>>();
    scatter_kernel<<<NROWS / 256, 256>>>(labels);
    intra_loss_kernel<<<NBLK, 256>>>(feats, center, out);
}

// round 6
// speedup vs baseline: 1.2239x; 1.2239x over previous
#include <cuda_runtime.h>
#include <cstdint>

// IntraLoss: loss = (1/N) * sum_n || features[n] - center[labels[n]] ||_2
// N=32768, C=1000, D=512. features f32 [N,D], labels int32 [N], center f32 [C,D].
//
// 1024 blocks x 256 threads. Block b owns 32 consecutive rows (64KB contiguous
// features). Features stream via cp.async.bulk into a 2x16KB SMEM ring
// (4 stages of 8 rows, double-buffered); one warp per row per stage.
// Center rows are read via LDG (L2-hot). Last block folds the partials.

#define NROWS 32768
#define NCLS  1000
#define DDIM  512
#define NBLK  1024
#define ROWS_PER_STAGE 8
#define NSTAGES 4
#define STAGE_BYTES (ROWS_PER_STAGE * DDIM * 4)   // 16384

__device__ float g_partials[NBLK];
__device__ unsigned int g_counter = 0;

__device__ __forceinline__ uint32_t s2u(const void* p) {
    return (uint32_t)__cvta_generic_to_shared(p);
}

__device__ __forceinline__ void mbar_init(uint32_t mbar, uint32_t count) {
    asm volatile("mbarrier.init.shared.b64 [%0], %1;" :: "r"(mbar), "r"(count) : "memory");
}

__device__ __forceinline__ void mbar_expect_tx(uint32_t mbar, uint32_t bytes) {
    asm volatile("mbarrier.arrive.expect_tx.shared.b64 _, [%0], %1;"
                 :: "r"(mbar), "r"(bytes) : "memory");
}

__device__ __forceinline__ void bulk_copy_g2s(uint32_t dst_smem, const void* src_gmem,
                                              uint32_t bytes, uint32_t mbar) {
    asm volatile(
        "cp.async.bulk.shared::cta.global.mbarrier::complete_tx::bytes [%0], [%1], %2, [%3];"
        :: "r"(dst_smem), "l"(src_gmem), "r"(bytes), "r"(mbar) : "memory");
}

__device__ __forceinline__ void mbar_wait(uint32_t mbar, uint32_t parity) {
    asm volatile(
        "{\n\t"
        ".reg .pred P;\n\t"
        "WAIT_%=:\n\t"
        "mbarrier.try_wait.parity.acquire.cta.shared::cta.b64 P, [%0], %1, 0x989680;\n\t"
        "@P bra.uni DONE_%=;\n\t"
        "bra.uni WAIT_%=;\n\t"
        "DONE_%=:\n\t"
        "}"
        :: "r"(mbar), "r"(parity) : "memory");
}

__global__ __launch_bounds__(256) void intra_loss_kernel(
    const float* __restrict__ feats,     // [N, D]
    const int* __restrict__ labels,      // [N] int32
    const float4* __restrict__ center,   // [C, D/4]
    float* __restrict__ out)
{
    __shared__ alignas(128) char sbuf[2][STAGE_BYTES];
    __shared__ alignas(8) unsigned long long mbar_store[2];
    __shared__ float wpart[8];
    __shared__ bool is_last;

    const int tid  = threadIdx.x;
    const int lane = tid & 31;
    const int wib  = tid >> 5;                    // warp = row within stage
    const int base = blockIdx.x * 32;             // first row of this block

    const uint32_t mb0 = s2u(&mbar_store[0]);
    const uint32_t mb1 = s2u(&mbar_store[1]);

    if (tid == 0) {
        mbar_init(mb0, 1);
        mbar_init(mb1, 1);
    }
    __syncthreads();

    // Kick off stages 0 and 1.
    if (tid == 0) {
        mbar_expect_tx(mb0, STAGE_BYTES);
        bulk_copy_g2s(s2u(&sbuf[0][0]), feats + (size_t)base * DDIM,
                      STAGE_BYTES, mb0);
        mbar_expect_tx(mb1, STAGE_BYTES);
        bulk_copy_g2s(s2u(&sbuf[1][0]), feats + (size_t)(base + 8) * DDIM,
                      STAGE_BYTES, mb1);
    }

    // Prefetch labels for my 4 rows (one per stage); uniform per warp.
    int lbl[NSTAGES];
    #pragma unroll
    for (int s = 0; s < NSTAGES; s++) {
        int v = labels[base + s * ROWS_PER_STAGE + wib];
        lbl[s] = min(max(v, 0), NCLS - 1);
    }

    float dsum = 0.0f;

    #pragma unroll
    for (int s = 0; s < NSTAGES; s++) {
        const uint32_t mb = (s & 1) ? mb1 : mb0;
        mbar_wait(mb, (s >> 1) & 1);

        const float4* srow = (const float4*)(&sbuf[s & 1][wib * (DDIM * 4)]);
        const float4* cr   = center + (size_t)lbl[s] * (DDIM / 4);

        float acc = 0.0f;
        #pragma unroll
        for (int j = 0; j < 4; j++) {
            float4 a = srow[lane + 32 * j];
            float4 b = __ldg(&cr[lane + 32 * j]);
            float dx = a.x - b.x;
            float dy = a.y - b.y;
            float dz = a.z - b.z;
            float dw = a.w - b.w;
            acc = fmaf(dx, dx, acc);
            acc = fmaf(dy, dy, acc);
            acc = fmaf(dz, dz, acc);
            acc = fmaf(dw, dw, acc);
        }

        #pragma unroll
        for (int sh = 16; sh > 0; sh >>= 1)
            acc += __shfl_xor_sync(0xffffffffu, acc, sh);
        if (lane == 0) dsum += sqrtf(acc);

        __syncthreads();   // everyone done reading sbuf[s&1]

        if (s < NSTAGES - 2 && tid == 0) {
            mbar_expect_tx(mb, STAGE_BYTES);
            bulk_copy_g2s(s2u(&sbuf[s & 1][0]),
                          feats + (size_t)(base + (s + 2) * ROWS_PER_STAGE) * DDIM,
                          STAGE_BYTES, mb);
        }
    }

    if (lane == 0) wpart[wib] = dsum;
    __syncthreads();

    if (tid == 0) {
        float sum = 0.0f;
        #pragma unroll
        for (int i = 0; i < 8; i++) sum += wpart[i];
        g_partials[blockIdx.x] = sum;
        __threadfence();
        unsigned int old = atomicAdd(&g_counter, 1u);
        is_last = (old == NBLK - 1);
    }
    __syncthreads();

    if (is_last) {
        float v = 0.0f;
        #pragma unroll
        for (int i = 0; i < 4; i++)
            v += g_partials[tid + i * 256];

        #pragma unroll
        for (int sh = 16; sh > 0; sh >>= 1)
            v += __shfl_xor_sync(0xffffffffu, v, sh);

        if (lane == 0) wpart[wib] = v;
        __syncthreads();

        if (tid == 0) {
            float w = 0.0f;
            #pragma unroll
            for (int i = 0; i < 8; i++) w += wpart[i];
            out[0] = w * (1.0f / (float)NROWS);
            g_counter = 0;   // reset for next graph replay
        }
    }
}

extern "C" void kernel_launch(void* const* d_in, const int* in_sizes, int n_in,
                              void* d_out, int out_size)
{
    const float* feats   = (const float*)d_in[0];
    const int* labels    = (const int*)d_in[1];
    const float4* center = (const float4*)d_in[2];
    float* out           = (float*)d_out;

    intra_loss_kernel<<<NBLK, 256>>>(feats, labels, center, out);
}

// round 7
// speedup vs baseline: 1.6078x; 1.3137x over previous
#include <cuda_runtime.h>

// IntraLoss: loss = (1/N) * sum_n || features[n] - center[labels[n]] ||_2
// N=32768, C=1000, D=512. features f32 [N,D], labels int32 [N], center f32 [C,D].
//
// 1024 blocks x 256 threads, single wave. Each warp: 4 rows, 8 lanes/row.
// Inner loop = 4 macro-iterations, each batch-loading 4 feature float4 +
// 4 center float4 into register arrays (8 LDG.128 in flight per thread)
// before computing. Last block folds the 1024 partials (no 2nd launch).

#define NROWS 32768
#define NCLS  1000
#define DDIM  512
#define NBLK  1024

__device__ float g_partials[NBLK];
__device__ unsigned int g_counter = 0;

__global__ __launch_bounds__(256) void intra_loss_kernel(
    const float4* __restrict__ feats,    // [N, D/4]
    const int* __restrict__ labels,      // [N] int32
    const float4* __restrict__ center,   // [C, D/4]
    float* __restrict__ out)
{
    const int lane  = threadIdx.x & 31;
    const int wib   = threadIdx.x >> 5;                      // 0..7
    const int warpG = (blockIdx.x << 3) + wib;               // 0..8191
    const int g     = lane >> 3;                             // group 0..3
    const int l     = lane & 7;                              // lane in group
    const int row   = (warpG << 2) + g;                      // 4 rows per warp

    int lbl = labels[row];
    lbl = min(max(lbl, 0), NCLS - 1);

    const float4* fr = feats  + (size_t)row * (DDIM / 4) + l;
    const float4* cr = center + (size_t)lbl * (DDIM / 4) + l;

    float acc = 0.0f;

    #pragma unroll
    for (int j = 0; j < 4; j++) {
        // Batch-issue 8 independent 16B loads before any compute.
        float4 A[4], B[4];
        #pragma unroll
        for (int k = 0; k < 4; k++)
            A[k] = __ldcs(fr + (4 * j + k) * 8);
        #pragma unroll
        for (int k = 0; k < 4; k++)
            B[k] = __ldg(cr + (4 * j + k) * 8);

        #pragma unroll
        for (int k = 0; k < 4; k++) {
            float dx = A[k].x - B[k].x;
            float dy = A[k].y - B[k].y;
            float dz = A[k].z - B[k].z;
            float dw = A[k].w - B[k].w;
            acc = fmaf(dx, dx, acc);
            acc = fmaf(dy, dy, acc);
            acc = fmaf(dz, dz, acc);
            acc = fmaf(dw, dw, acc);
        }
    }

    // reduce within 8-lane group (all 4 rows in parallel)
    acc += __shfl_xor_sync(0xffffffffu, acc, 1);
    acc += __shfl_xor_sync(0xffffffffu, acc, 2);
    acc += __shfl_xor_sync(0xffffffffu, acc, 4);

    // one sqrt per row (group leaders), zeros elsewhere
    float d = (l == 0) ? sqrtf(acc) : 0.0f;

    // sum the 4 row-distances across groups
    d += __shfl_xor_sync(0xffffffffu, d, 8);
    d += __shfl_xor_sync(0xffffffffu, d, 16);

    __shared__ float smem[8];
    __shared__ bool is_last;
    if (lane == 0) smem[wib] = d;
    __syncthreads();

    if (threadIdx.x == 0) {
        float s = 0.0f;
        #pragma unroll
        for (int i = 0; i < 8; i++) s += smem[i];
        g_partials[blockIdx.x] = s;
        __threadfence();
        unsigned int old = atomicAdd(&g_counter, 1u);
        is_last = (old == NBLK - 1);
    }
    __syncthreads();

    if (is_last) {
        float v = 0.0f;
        #pragma unroll
        for (int i = 0; i < 4; i++)
            v += g_partials[threadIdx.x + i * 256];

        #pragma unroll
        for (int s = 16; s > 0; s >>= 1)
            v += __shfl_xor_sync(0xffffffffu, v, s);

        __shared__ float smem2[8];
        if (lane == 0) smem2[wib] = v;
        __syncthreads();

        if (threadIdx.x == 0) {
            float w = 0.0f;
            #pragma unroll
            for (int i = 0; i < 8; i++) w += smem2[i];
            out[0] = w * (1.0f / (float)NROWS);
            g_counter = 0;   // reset for next graph replay
        }
    }
}

extern "C" void kernel_launch(void* const* d_in, const int* in_sizes, int n_in,
                              void* d_out, int out_size)
{
    const float4* feats  = (const float4*)d_in[0];
    const int* labels    = (const int*)d_in[1];
    const float4* center = (const float4*)d_in[2];
    float* out           = (float*)d_out;

    intra_loss_kernel<<<NBLK, 256>>>(feats, labels, center, out);
}